// round 5
// baseline (speedup 1.0000x reference)
#include <cuda_runtime.h>

#define B_   4
#define C_   2048
#define DM_  128
#define H_   8
#define DPH_ 16
#define K_   7

// Scratch (device globals: no allocation allowed in kernel_launch)
__device__ float g_kc[B_ * C_ * DM_];   // conv(key)   (b, c_out, l)
__device__ float g_vc[B_ * C_ * DM_];   // conv(value) (b, c_out, l)
__device__ float g_at[B_ * C_ * DM_];   // attention out, merged heads (b, c, h*16+d)

// ---------------------------------------------------------------------------
// Causal conv1d as GEMM: OUT[b,m,l] = bias[m] + sum_{ci,t} W[m,ci,t]*Xpad[b,ci,l+t]
// Xpad left-padded by 6.  M-tile=64, N-tile=128 (one batch's full L), K chunk = 8 ci (=56 taps).
// blockIdx: x = m-tile (32), y = batch (4), z = which conv (2). 256 threads.
// ---------------------------------------------------------------------------
__global__ __launch_bounds__(256)
void conv_kernel(const float* __restrict__ key, const float* __restrict__ value,
                 const float* __restrict__ wk, const float* __restrict__ bk,
                 const float* __restrict__ wv, const float* __restrict__ bv)
{
    const float *X, *W, *bias;
    float* OUT;
    if (blockIdx.z == 0) { X = key;   W = wk; bias = bk; OUT = g_kc; }
    else                 { X = value; W = wv; bias = bv; OUT = g_vc; }

    const int b   = blockIdx.y;
    const int m0  = blockIdx.x * 64;
    const int tid = threadIdx.x;
    const int tm  = tid >> 4;   // 0..15  -> m = m0 + tm*4 + r
    const int tl  = tid & 15;   // 0..15  -> l = tl*8 + j

    // ws: [r=ci*7+t][m], row stride 68 floats (272B, 16B aligned, limits store conflicts)
    __shared__ float ws[56 * 68];
    // xs: [ci][i], i in [0,134): xs[ci][i] = X[b, ci0+ci, i-6] (0 for i<6). row stride 144.
    __shared__ float xs[8 * 144];

    const float* Xb = X + (size_t)b * (C_ * DM_);
    const float* Wm = W + (size_t)m0 * (C_ * K_);

    // Per-thread load descriptors (fixed across K chunks)
    int woff[14];   // global offset within Wm for chunk 0
    int wso[14];    // smem store offset
    #pragma unroll
    for (int jj = 0; jj < 14; ++jj) {
        int e = tid + 256 * jj;         // e < 3584 = 64*56 always
        int m = e / 56, r = e % 56;
        woff[jj] = m * (C_ * K_) + r;
        wso[jj]  = r * 68 + m;
    }
    int  xoff[5], xso[5];
    bool xload[5], xstore[5];
    #pragma unroll
    for (int jj = 0; jj < 5; ++jj) {
        int e = tid + 256 * jj;
        xstore[jj] = (e < 1072);        // 8*134
        int ci = e / 134, ii = e % 134;
        xload[jj] = xstore[jj] && (ii >= 6);
        xoff[jj]  = ci * DM_ + ii - 6;
        xso[jj]   = ci * 144 + ii;
    }

    float acc[4][8];
    #pragma unroll
    for (int r = 0; r < 4; ++r)
        #pragma unroll
        for (int j = 0; j < 8; ++j) acc[r][j] = 0.f;

    // Register prefetch of chunk 0
    float wreg[14], xreg[5];
    #pragma unroll
    for (int jj = 0; jj < 14; ++jj) wreg[jj] = Wm[woff[jj]];
    #pragma unroll
    for (int jj = 0; jj < 5; ++jj)  xreg[jj] = xload[jj] ? Xb[xoff[jj]] : 0.f;

    for (int kc = 0; kc < C_ / 8; ++kc) {
        __syncthreads();
        #pragma unroll
        for (int jj = 0; jj < 14; ++jj) ws[wso[jj]] = wreg[jj];
        #pragma unroll
        for (int jj = 0; jj < 5; ++jj)  if (xstore[jj]) xs[xso[jj]] = xreg[jj];
        __syncthreads();

        if (kc + 1 < C_ / 8) {          // prefetch next chunk (overlaps compute)
            const int wo = (kc + 1) * 56;
            const int xo = (kc + 1) * (8 * DM_);
            #pragma unroll
            for (int jj = 0; jj < 14; ++jj) wreg[jj] = Wm[woff[jj] + wo];
            #pragma unroll
            for (int jj = 0; jj < 5; ++jj)  xreg[jj] = xload[jj] ? Xb[xoff[jj] + xo] : 0.f;
        }

        #pragma unroll 2
        for (int ci = 0; ci < 8; ++ci) {
            float xb[14];
            #pragma unroll
            for (int j = 0; j < 14; ++j) xb[j] = xs[ci * 144 + tl * 8 + j];
            #pragma unroll
            for (int t = 0; t < 7; ++t) {
                float4 a = *(const float4*)&ws[(ci * 7 + t) * 68 + tm * 4];
                #pragma unroll
                for (int j = 0; j < 8; ++j) {
                    const float xv = xb[t + j];
                    acc[0][j] = fmaf(a.x, xv, acc[0][j]);
                    acc[1][j] = fmaf(a.y, xv, acc[1][j]);
                    acc[2][j] = fmaf(a.z, xv, acc[2][j]);
                    acc[3][j] = fmaf(a.w, xv, acc[3][j]);
                }
            }
        }
    }

    #pragma unroll
    for (int r = 0; r < 4; ++r) {
        const int m = m0 + tm * 4 + r;
        const float bb = bias[m];
        float* op = OUT + ((size_t)b * C_ + m) * DM_ + tl * 8;
        float4 o0 = make_float4(acc[r][0] + bb, acc[r][1] + bb, acc[r][2] + bb, acc[r][3] + bb);
        float4 o1 = make_float4(acc[r][4] + bb, acc[r][5] + bb, acc[r][6] + bb, acc[r][7] + bb);
        *(float4*)(op)     = o0;
        *(float4*)(op + 4) = o1;
    }
}

// ---------------------------------------------------------------------------
// Fast 2^y on the fma/alu pipes (avoids MUFU bottleneck: 134M exps).
// y <= 0 here.  rint-split, degree-5 Taylor on [-0.5,0.5] (rel err ~2.4e-6),
// exponent via integer construct.  ~9 fixed-latency ops.
// ---------------------------------------------------------------------------
__device__ __forceinline__ float fexp2(float y)
{
    y = fmaxf(y, -126.0f);
    const float n = rintf(y);
    const float f = y - n;                 // [-0.5, 0.5]
    float p = 1.3333558146e-3f;
    p = fmaf(p, f, 9.6181291076e-3f);
    p = fmaf(p, f, 5.5504108665e-2f);
    p = fmaf(p, f, 2.4022650696e-1f);
    p = fmaf(p, f, 6.9314718056e-1f);
    p = fmaf(p, f, 1.0f);
    const int ni = (int)n;                 // [-126, 0]
    const float sc = __int_as_float((ni + 127) << 23);
    return sc * p;
}

// ---------------------------------------------------------------------------
// Flash-style attention, fp32. 1 thread = 1 query row (DPH=16 in registers).
// Online softmax in log2 domain (scale 1/4 * log2e folded into q).
// grid (C/128, H, B), 128 threads.
// ---------------------------------------------------------------------------
__global__ __launch_bounds__(128)
void attn_kernel(const float* __restrict__ query)
{
    const int b   = blockIdx.z;
    const int h   = blockIdx.y;
    const int tid = threadIdx.x;
    const int c   = blockIdx.x * 128 + tid;

    __shared__ float Ks[32][16];
    __shared__ float Vs[32][16];

    const float scale = 0.25f * 1.4426950408889634f;   // 1/sqrt(16) * log2(e)
    float q[16];
    {
        const float4* qp = (const float4*)(query + ((size_t)(b * C_) + c) * DM_ + h * DPH_);
        float4 q0 = qp[0], q1 = qp[1], q2 = qp[2], q3 = qp[3];
        q[0]=q0.x*scale; q[1]=q0.y*scale; q[2]=q0.z*scale; q[3]=q0.w*scale;
        q[4]=q1.x*scale; q[5]=q1.y*scale; q[6]=q1.z*scale; q[7]=q1.w*scale;
        q[8]=q2.x*scale; q[9]=q2.y*scale; q[10]=q2.z*scale; q[11]=q2.w*scale;
        q[12]=q3.x*scale; q[13]=q3.y*scale; q[14]=q3.z*scale; q[15]=q3.w*scale;
    }

    float acc[16];
    #pragma unroll
    for (int d = 0; d < 16; ++d) acc[d] = 0.f;
    float mmax = -3.0e38f, ssum = 0.f;

    const size_t kvbase = (size_t)(b * C_) * DM_ + h * DPH_;
    const int jrow = tid >> 2;            // 0..31
    const int d4   = (tid & 3) * 4;       // 0,4,8,12

    for (int kb = 0; kb < C_ / 32; ++kb) {
        __syncthreads();
        {
            const size_t idx = kvbase + (size_t)(kb * 32 + jrow) * DM_ + d4;
            *(float4*)&Ks[jrow][d4] = *(const float4*)(g_kc + idx);
            *(float4*)&Vs[jrow][d4] = *(const float4*)(g_vc + idx);
        }
        __syncthreads();

        float p[32];
        float cmax = -3.0e38f;
        #pragma unroll
        for (int j = 0; j < 32; ++j) {
            float4 k0 = *(const float4*)&Ks[j][0];
            float4 k1 = *(const float4*)&Ks[j][4];
            float4 k2 = *(const float4*)&Ks[j][8];
            float4 k3 = *(const float4*)&Ks[j][12];
            float s;
            s = q[0] * k0.x;
            s = fmaf(q[1],  k0.y, s); s = fmaf(q[2],  k0.z, s); s = fmaf(q[3],  k0.w, s);
            s = fmaf(q[4],  k1.x, s); s = fmaf(q[5],  k1.y, s); s = fmaf(q[6],  k1.z, s); s = fmaf(q[7],  k1.w, s);
            s = fmaf(q[8],  k2.x, s); s = fmaf(q[9],  k2.y, s); s = fmaf(q[10], k2.z, s); s = fmaf(q[11], k2.w, s);
            s = fmaf(q[12], k3.x, s); s = fmaf(q[13], k3.y, s); s = fmaf(q[14], k3.z, s); s = fmaf(q[15], k3.w, s);
            p[j] = s;
            cmax = fmaxf(cmax, s);
        }

        const float newm = fmaxf(mmax, cmax);
        const float corr = fexp2(mmax - newm);
        mmax = newm;
        ssum *= corr;
        #pragma unroll
        for (int d = 0; d < 16; ++d) acc[d] *= corr;

        #pragma unroll
        for (int j = 0; j < 32; ++j) {
            const float pj = fexp2(p[j] - newm);
            ssum += pj;
            float4 v0 = *(const float4*)&Vs[j][0];
            float4 v1 = *(const float4*)&Vs[j][4];
            float4 v2 = *(const float4*)&Vs[j][8];
            float4 v3 = *(const float4*)&Vs[j][12];
            acc[0]  = fmaf(pj, v0.x, acc[0]);  acc[1]  = fmaf(pj, v0.y, acc[1]);
            acc[2]  = fmaf(pj, v0.z, acc[2]);  acc[3]  = fmaf(pj, v0.w, acc[3]);
            acc[4]  = fmaf(pj, v1.x, acc[4]);  acc[5]  = fmaf(pj, v1.y, acc[5]);
            acc[6]  = fmaf(pj, v1.z, acc[6]);  acc[7]  = fmaf(pj, v1.w, acc[7]);
            acc[8]  = fmaf(pj, v2.x, acc[8]);  acc[9]  = fmaf(pj, v2.y, acc[9]);
            acc[10] = fmaf(pj, v2.z, acc[10]); acc[11] = fmaf(pj, v2.w, acc[11]);
            acc[12] = fmaf(pj, v3.x, acc[12]); acc[13] = fmaf(pj, v3.y, acc[13]);
            acc[14] = fmaf(pj, v3.z, acc[14]); acc[15] = fmaf(pj, v3.w, acc[15]);
        }
    }

    const float inv = 1.0f / ssum;
    float* op = g_at + ((size_t)(b * C_) + c) * DM_ + h * DPH_;
    #pragma unroll
    for (int d = 0; d < 16; d += 4) {
        float4 o = make_float4(acc[d] * inv, acc[d + 1] * inv, acc[d + 2] * inv, acc[d + 3] * inv);
        *(float4*)(op + d) = o;
    }
}

// ---------------------------------------------------------------------------
// out[n,o] = sum_k g_at[n,k] * lin_w[o,k] + lin_b[o].  16 rows x 128 cols per block.
// ---------------------------------------------------------------------------
__global__ __launch_bounds__(128)
void linear_kernel(const float* __restrict__ lw, const float* __restrict__ lb,
                   float* __restrict__ out)
{
    const int row0 = blockIdx.x * 16;
    const int tid  = threadIdx.x;

    __shared__ float As[16][128];
    __shared__ float Ws[32][129];     // pad to kill store conflicts

    #pragma unroll
    for (int r = 0; r < 16; ++r)
        As[r][tid] = g_at[(size_t)(row0 + r) * DM_ + tid];

    float acc[16];
    #pragma unroll
    for (int r = 0; r < 16; ++r) acc[r] = 0.f;

    for (int k0 = 0; k0 < 128; k0 += 32) {
        __syncthreads();
        #pragma unroll
        for (int jj = 0; jj < 32; ++jj) {
            const int e = tid + 128 * jj;
            const int o = e >> 5, kk = e & 31;
            Ws[kk][o] = lw[o * 128 + k0 + kk];
        }
        __syncthreads();
        #pragma unroll
        for (int kk = 0; kk < 32; ++kk) {
            const float w = Ws[kk][tid];
            #pragma unroll
            for (int r = 0; r < 16; ++r)
                acc[r] = fmaf(As[r][k0 + kk], w, acc[r]);
        }
    }

    #pragma unroll
    for (int r = 0; r < 16; ++r)
        out[(size_t)(row0 + r) * DM_ + tid] = acc[r] + lb[tid];
}

// ---------------------------------------------------------------------------
extern "C" void kernel_launch(void* const* d_in, const int* in_sizes, int n_in,
                              void* d_out, int out_size)
{
    const float* query = (const float*)d_in[0];
    const float* key   = (const float*)d_in[1];
    const float* value = (const float*)d_in[2];
    const float* wk    = (const float*)d_in[3];
    const float* bk    = (const float*)d_in[4];
    const float* wv    = (const float*)d_in[5];
    const float* bv    = (const float*)d_in[6];
    const float* lw    = (const float*)d_in[7];
    const float* lb    = (const float*)d_in[8];
    float* out = (float*)d_out;

    conv_kernel<<<dim3(C_ / 64, B_, 2), 256>>>(key, value, wk, bk, wv, bv);
    attn_kernel<<<dim3(C_ / 128, H_, B_), 128>>>(query);
    linear_kernel<<<(B_ * C_) / 16, 128>>>(lw, lb, out);
}